// round 9
// baseline (speedup 1.0000x reference)
#include <cuda_runtime.h>
#include <cuda_bf16.h>
#include <cuda_fp16.h>
#include <cstdint>

#define Bn  16
#define Qn  64
#define Kn  1024
#define Dn  256
#define Hn  128
#define DVn 256

// Scratch (device globals; no allocation allowed in kernel_launch)
__device__ float g_kproj[Bn * Kn * Hn];        // 8 MB
__device__ float g_qproj[Bn * Qn * Hn];        // 0.5 MB
__device__ float g_scores[Bn * Qn * Kn];       // 4 MB (scores, then attn)
__device__ float g_part[8][Bn][Qn][DVn];       // 8 MB AV partials (zero-init;
                                               // chunks beyond vlen are never
                                               // written and stay exactly 0)

// ---------------------------------------------------------------------------
// mma.sync m16n8k16 bf16 (row.col) with fp32 accumulate. compute_80+ PTX,
// so it passes the harness's compute_100 virtual target (tcgen05 does not).
// ---------------------------------------------------------------------------
__device__ __forceinline__ void mma16816(float* d, const uint32_t* a,
                                         const uint32_t* b) {
    asm volatile(
        "mma.sync.aligned.m16n8k16.row.col.f32.bf16.bf16.f32 "
        "{%0,%1,%2,%3}, {%4,%5,%6,%7}, {%8,%9}, {%0,%1,%2,%3};"
        : "+f"(d[0]), "+f"(d[1]), "+f"(d[2]), "+f"(d[3])
        : "r"(a[0]), "r"(a[1]), "r"(a[2]), "r"(a[3]), "r"(b[0]), "r"(b[1]));
}

__device__ __forceinline__ __nv_bfloat162 hi2(float a, float b) {
    return __halves2bfloat162(__float2bfloat16(a), __float2bfloat16(b));
}
__device__ __forceinline__ __nv_bfloat162 lo2(float a, float b) {
    return __halves2bfloat162(
        __float2bfloat16(a - __bfloat162float(__float2bfloat16(a))),
        __float2bfloat16(b - __bfloat162float(__float2bfloat16(b))));
}

#define KC 32
// Pad = 40 bf16 (even -> rows stay 4B-aligned for uint32_t fragment loads;
// R8's odd pad of 33 crashed on misaligned address).
// A fragments: gid stride = 8 rows = 320 words; 320g mod 32 = 0 BUT the two
// k-halves (+8 bf16) and row pairs split accesses; measured fine in R4-R7.
// B fragments: gid stride = 1 row = 20 words; 20g mod 32 distinct for g=0..7,
// tig adds disjoint 4-word windows -> conflict-free (R8's "8-way" claim used
// the wrong stride).
#define APAD 40

// ---------------------------------------------------------------------------
// Projection P[r, h] = sum_d X[r, d] * W[d, h] via HMMA with split-bf16
// (x = hi + lo; X*W ~= Xh*Wh + Xl*Wh + Xh*Wl, per-term err ~eps^2).
// Grid = 136 CTAs: cid<128 -> keys/Wk/g_kproj (16384 rows), else queries.
// CTA tile 128 rows x 128 cols; 8 warps as 2(M) x 4(N); warp tile 64x32.
// ---------------------------------------------------------------------------
__global__ void __launch_bounds__(256, 1) proj_mma_kernel(
    const float* __restrict__ keys, const float* __restrict__ queries,
    const float* __restrict__ Wk, const float* __restrict__ Wq) {
    __shared__ __align__(16) __nv_bfloat16 sAhi[128][APAD];
    __shared__ __align__(16) __nv_bfloat16 sAlo[128][APAD];
    __shared__ __align__(16) __nv_bfloat16 sBhi[128][APAD];  // [n][k]
    __shared__ __align__(16) __nv_bfloat16 sBlo[128][APAD];

    const int tid  = threadIdx.x;
    const int wid  = tid >> 5;
    const int lane = tid & 31;
    const int cid  = blockIdx.x;

    const float* X;
    const float* W;
    float* P;
    int row0;
    if (cid < 128) {
        X = keys; W = Wk; P = g_kproj; row0 = cid * 128;
    } else {
        X = queries; W = Wq; P = g_qproj; row0 = (cid - 128) * 128;
    }

    const int wm  = (wid & 1) * 64;
    const int wn  = (wid >> 1) * 32;
    const int gid = lane >> 2;
    const int tig = lane & 3;

    float acc[4][4][4];
#pragma unroll
    for (int im = 0; im < 4; im++)
#pragma unroll
        for (int in2 = 0; in2 < 4; in2++)
#pragma unroll
            for (int r = 0; r < 4; r++) acc[im][in2][r] = 0.f;

    for (int kc = 0; kc < Dn; kc += KC) {
#pragma unroll
        for (int i = 0; i < 4; i++) {
            int idx = tid + i * 256;
            int r = idx >> 3, kq = idx & 7;
            float4 v = *(const float4*)&X[(size_t)(row0 + r) * Dn + kc + kq * 4];
            __nv_bfloat162* ph = (__nv_bfloat162*)&sAhi[r][kq * 4];
            ph[0] = hi2(v.x, v.y);
            ph[1] = hi2(v.z, v.w);
            __nv_bfloat162* pl = (__nv_bfloat162*)&sAlo[r][kq * 4];
            pl[0] = lo2(v.x, v.y);
            pl[1] = lo2(v.z, v.w);
        }
#pragma unroll
        for (int i = 0; i < 4; i++) {
            int idx = tid + i * 256;
            int k = idx >> 5, n4 = idx & 31;
            float4 w = *(const float4*)&W[(size_t)(kc + k) * Hn + n4 * 4];
            float wf[4] = {w.x, w.y, w.z, w.w};
#pragma unroll
            for (int j = 0; j < 4; j++) {
                __nv_bfloat16 h = __float2bfloat16(wf[j]);
                sBhi[n4 * 4 + j][k] = h;
                sBlo[n4 * 4 + j][k] =
                    __float2bfloat16(wf[j] - __bfloat162float(h));
            }
        }
        __syncthreads();

#pragma unroll
        for (int s = 0; s < 2; s++) {
            const int kb = s * 16 + tig * 2;

            uint32_t Ah[4][4], Al[4][4];
#pragma unroll
            for (int im = 0; im < 4; im++) {
                int r = wm + im * 16 + gid;
                Ah[im][0] = *(const uint32_t*)&sAhi[r][kb];
                Ah[im][1] = *(const uint32_t*)&sAhi[r + 8][kb];
                Ah[im][2] = *(const uint32_t*)&sAhi[r][kb + 8];
                Ah[im][3] = *(const uint32_t*)&sAhi[r + 8][kb + 8];
                Al[im][0] = *(const uint32_t*)&sAlo[r][kb];
                Al[im][1] = *(const uint32_t*)&sAlo[r + 8][kb];
                Al[im][2] = *(const uint32_t*)&sAlo[r][kb + 8];
                Al[im][3] = *(const uint32_t*)&sAlo[r + 8][kb + 8];
            }
            uint32_t Bh[4][2], Bl[4][2];
#pragma unroll
            for (int in2 = 0; in2 < 4; in2++) {
                int n = wn + in2 * 8 + gid;
                Bh[in2][0] = *(const uint32_t*)&sBhi[n][kb];
                Bh[in2][1] = *(const uint32_t*)&sBhi[n][kb + 8];
                Bl[in2][0] = *(const uint32_t*)&sBlo[n][kb];
                Bl[in2][1] = *(const uint32_t*)&sBlo[n][kb + 8];
            }
#pragma unroll
            for (int im = 0; im < 4; im++) {
#pragma unroll
                for (int in2 = 0; in2 < 4; in2++) {
                    mma16816(acc[im][in2], Ah[im], Bh[in2]);
                    mma16816(acc[im][in2], Al[im], Bh[in2]);
                    mma16816(acc[im][in2], Ah[im], Bl[in2]);
                }
            }
        }
        __syncthreads();
    }

#pragma unroll
    for (int im = 0; im < 4; im++) {
        int r_lo = row0 + wm + im * 16 + gid;
#pragma unroll
        for (int in2 = 0; in2 < 4; in2++) {
            int c = wn + in2 * 8 + tig * 2;
            *(float2*)&P[(size_t)r_lo * Hn + c] =
                make_float2(acc[im][in2][0], acc[im][in2][1]);
            *(float2*)&P[(size_t)(r_lo + 8) * Hn + c] =
                make_float2(acc[im][in2][2], acc[im][in2][3]);
        }
    }
}

// ---------------------------------------------------------------------------
// scores[b, q, k] = sum_h wv[h] * tanh(qproj[b,q,h] + kproj[b,k,h])
// CTA = (k-tile 32, q-half 32, b). tanh via tanh.approx.f16x2 — one MUFU
// op per 2 elements (adds in fp32, pack->tanh->unpack, fp32 accumulate).
// Expected extra error ~2e-4 on scores -> ~1e-4 output rel err.
// ---------------------------------------------------------------------------
__global__ void scores_kernel(const float* __restrict__ wv) {
    const int b   = blockIdx.z;
    const int qh  = blockIdx.y * 32;
    const int k0  = blockIdx.x * 32;
    const int tid = threadIdx.x;

    __shared__ __align__(16) float sQ[32][Hn];
    __shared__ __align__(16) float sK[32][132];
    __shared__ __align__(16) float sWv[Hn];

    {
        const float4* src =
            (const float4*)(g_qproj + ((size_t)b * Qn + qh) * Hn);
        float4* dst = (float4*)&sQ[0][0];
#pragma unroll
        for (int i = 0; i < 4; i++) {
            int j = tid + i * 256;
            dst[j] = src[j];
        }
    }
    {
        const float4* src =
            (const float4*)(g_kproj + ((size_t)b * Kn + k0) * Hn);
#pragma unroll
        for (int i = 0; i < 4; i++) {
            int j   = tid + i * 256;
            int row = j >> 5;
            int c4  = j & 31;
            *(float4*)&sK[row][c4 * 4] = src[j];
        }
    }
    if (tid < Hn) sWv[tid] = wv[tid];
    __syncthreads();

    const int kk = tid & 31;
    const int q0 = (tid >> 5) * 4;
    float sc[4];
    sc[0] = sc[1] = sc[2] = sc[3] = 0.f;

#pragma unroll 4
    for (int h = 0; h < Hn; h += 4) {
        float4 kv = *(const float4*)&sK[kk][h];
        float4 w4 = *(const float4*)&sWv[h];
#pragma unroll
        for (int qi = 0; qi < 4; qi++) {
            float4 qv = *(const float4*)&sQ[q0 + qi][h];
            float x0 = qv.x + kv.x;
            float x1 = qv.y + kv.y;
            float x2 = qv.z + kv.z;
            float x3 = qv.w + kv.w;
            uint32_t pa, pb, ta, tb;
            // cvt.rn.f16x2.f32 d, a, b -> d.hi = cvt(a), d.lo = cvt(b)
            asm("cvt.rn.f16x2.f32 %0, %1, %2;" : "=r"(pa) : "f"(x1), "f"(x0));
            asm("cvt.rn.f16x2.f32 %0, %1, %2;" : "=r"(pb) : "f"(x3), "f"(x2));
            asm("tanh.approx.f16x2 %0, %1;" : "=r"(ta) : "r"(pa));
            asm("tanh.approx.f16x2 %0, %1;" : "=r"(tb) : "r"(pb));
            float2 fa = __half22float2(*reinterpret_cast<__half2*>(&ta));
            float2 fb = __half22float2(*reinterpret_cast<__half2*>(&tb));
            sc[qi] += w4.x * fa.x + w4.y * fa.y + w4.z * fb.x + w4.w * fb.y;
        }
    }

    float* srow = g_scores + ((size_t)b * Qn + qh) * Kn + k0 + kk;
#pragma unroll
    for (int qi = 0; qi < 4; qi++) {
        srow[(size_t)(q0 + qi) * Kn] = sc[qi];
    }
}

// ---------------------------------------------------------------------------
// Masked softmax over K=1024, in place in g_scores.
// Invalid lanes (k >= vlen) -> exactly 0 after exp underflow.
// ---------------------------------------------------------------------------
__global__ void softmax_kernel(const int* __restrict__ vlen) {
    const int b   = blockIdx.y;
    const int q   = blockIdx.x;
    const int tid = threadIdx.x;

    float* row   = g_scores + ((size_t)b * Qn + q) * Kn;
    const int vl = vlen[b];

    float4 s      = ((const float4*)row)[tid];
    const int kb  = tid * 4;
    if (kb + 0 >= vl) s.x = -1e6f;
    if (kb + 1 >= vl) s.y = -1e6f;
    if (kb + 2 >= vl) s.z = -1e6f;
    if (kb + 3 >= vl) s.w = -1e6f;

    __shared__ float redm[8];
    __shared__ float reds[8];

    float m = fmaxf(fmaxf(s.x, s.y), fmaxf(s.z, s.w));
#pragma unroll
    for (int o = 16; o; o >>= 1) m = fmaxf(m, __shfl_xor_sync(0xffffffffu, m, o));
    if ((tid & 31) == 0) redm[tid >> 5] = m;
    __syncthreads();
    float M = redm[0];
#pragma unroll
    for (int i = 1; i < 8; i++) M = fmaxf(M, redm[i]);

    float e0 = __expf(s.x - M);
    float e1 = __expf(s.y - M);
    float e2 = __expf(s.z - M);
    float e3 = __expf(s.w - M);

    float t = (e0 + e1) + (e2 + e3);
#pragma unroll
    for (int o = 16; o; o >>= 1) t += __shfl_xor_sync(0xffffffffu, t, o);
    if ((tid & 31) == 0) reds[tid >> 5] = t;
    __syncthreads();
    float S = reds[0];
#pragma unroll
    for (int i = 1; i < 8; i++) S += reds[i];

    float inv = 1.0f / S;
    ((float4*)row)[tid] = make_float4(e0 * inv, e1 * inv, e2 * inv, e3 * inv);
}

// ---------------------------------------------------------------------------
// AV as HMMA GEMM. Grid = (k-chunk 8, n-half 2, b 16) = 256 CTAs; each
// does 64q x 128dv over 128 k (halved staging vs R7 -> 2x parallelism).
// Chunks beyond vlen return early; their g_part slice stays exactly 0.
// 8 warps as 2(M) x 4(N); warp tile 32x32.
// ---------------------------------------------------------------------------
__global__ void __launch_bounds__(256) av_mma_kernel(
    const float* __restrict__ V, const int* __restrict__ vlen) {
    const int b  = blockIdx.z;
    const int ck = blockIdx.x;
    const int n0 = blockIdx.y * 128;
    const int k0 = ck * 128;
    if (k0 >= vlen[b]) return;  // uniform per CTA

    __shared__ __align__(16) __nv_bfloat16 sAh[64][APAD];   // attn hi
    __shared__ __align__(16) __nv_bfloat16 sAl[64][APAD];   // attn lo
    __shared__ __align__(16) __nv_bfloat16 sVh[128][APAD];  // V^T hi [n][k]
    __shared__ __align__(16) __nv_bfloat16 sVl[128][APAD];  // V^T lo

    const int tid  = threadIdx.x;
    const int wid  = tid >> 5;
    const int lane = tid & 31;
    const int gid  = lane >> 2;
    const int tig  = lane & 3;
    const int wm   = (wid & 1) * 32;   // 2 x 32 = 64 q
    const int wn   = (wid >> 1) * 32;  // 4 x 32 = 128 dv

    float acc[2][4][4];
#pragma unroll
    for (int im = 0; im < 2; im++)
#pragma unroll
        for (int j = 0; j < 4; j++)
#pragma unroll
            for (int r = 0; r < 4; r++) acc[im][j][r] = 0.f;

    const float* Ab = g_scores + ((size_t)b * Qn) * Kn + k0;
    const float* Vb = V + ((size_t)b * Kn + k0) * DVn + n0;

    for (int kc = 0; kc < 128; kc += KC) {
        // ---- stage attn chunk: 64 q x 32 k, hi/lo ----
#pragma unroll
        for (int i = 0; i < 2; i++) {
            int idx = tid + i * 256;          // 512 float4
            int r = idx >> 3, kq = idx & 7;
            float4 v = *(const float4*)&Ab[(size_t)r * Kn + kc + kq * 4];
            __nv_bfloat162* ph = (__nv_bfloat162*)&sAh[r][kq * 4];
            ph[0] = hi2(v.x, v.y);
            ph[1] = hi2(v.z, v.w);
            __nv_bfloat162* pl = (__nv_bfloat162*)&sAl[r][kq * 4];
            pl[0] = lo2(v.x, v.y);
            pl[1] = lo2(v.z, v.w);
        }
        // ---- stage V^T chunk: sV[n][k] = V[kc+k][n0+n], 32 k x 128 n ----
#pragma unroll
        for (int i = 0; i < 4; i++) {
            int idx = tid + i * 256;          // 1024 float4
            int k = idx >> 5, n4 = idx & 31;  // 32 float4 per k-row
            float4 w = *(const float4*)&Vb[(size_t)(kc + k) * DVn + n4 * 4];
            float wf[4] = {w.x, w.y, w.z, w.w};
#pragma unroll
            for (int j = 0; j < 4; j++) {
                __nv_bfloat16 h = __float2bfloat16(wf[j]);
                sVh[n4 * 4 + j][k] = h;
                sVl[n4 * 4 + j][k] =
                    __float2bfloat16(wf[j] - __bfloat162float(h));
            }
        }
        __syncthreads();

#pragma unroll
        for (int s = 0; s < 2; s++) {
            const int kb = s * 16 + tig * 2;

            uint32_t Ah2[2][4], Al2[2][4];
#pragma unroll
            for (int im = 0; im < 2; im++) {
                int r = wm + im * 16 + gid;
                Ah2[im][0] = *(const uint32_t*)&sAh[r][kb];
                Ah2[im][1] = *(const uint32_t*)&sAh[r + 8][kb];
                Ah2[im][2] = *(const uint32_t*)&sAh[r][kb + 8];
                Ah2[im][3] = *(const uint32_t*)&sAh[r + 8][kb + 8];
                Al2[im][0] = *(const uint32_t*)&sAl[r][kb];
                Al2[im][1] = *(const uint32_t*)&sAl[r + 8][kb];
                Al2[im][2] = *(const uint32_t*)&sAl[r][kb + 8];
                Al2[im][3] = *(const uint32_t*)&sAl[r + 8][kb + 8];
            }
#pragma unroll
            for (int j = 0; j < 4; j++) {
                int n = wn + j * 8 + gid;
                uint32_t Bh[2], Bl[2];
                Bh[0] = *(const uint32_t*)&sVh[n][kb];
                Bh[1] = *(const uint32_t*)&sVh[n][kb + 8];
                Bl[0] = *(const uint32_t*)&sVl[n][kb];
                Bl[1] = *(const uint32_t*)&sVl[n][kb + 8];
#pragma unroll
                for (int im = 0; im < 2; im++) {
                    mma16816(acc[im][j], Ah2[im], Bh);
                    mma16816(acc[im][j], Al2[im], Bh);
                    mma16816(acc[im][j], Ah2[im], Bl);
                }
            }
        }
        __syncthreads();
    }

    // ---- epilogue: partials to g_part[ck][b] (+ n0 column offset) ----
    float* Pb = &g_part[ck][b][0][0] + n0;
#pragma unroll
    for (int im = 0; im < 2; im++) {
        int r = wm + im * 16 + gid;
#pragma unroll
        for (int j = 0; j < 4; j++) {
            int c = wn + j * 8 + tig * 2;
            *(float2*)&Pb[(size_t)r * DVn + c] =
                make_float2(acc[im][j][0], acc[im][j][1]);
            *(float2*)&Pb[(size_t)(r + 8) * DVn + c] =
                make_float2(acc[im][j][2], acc[im][j][3]);
        }
    }
}

// ---------------------------------------------------------------------------
// out = sum over 8 k-chunk partials. 256 CTAs x 256 threads x 1 float4.
// ---------------------------------------------------------------------------
__global__ void reduce_kernel(float* __restrict__ out) {
    const int idx = blockIdx.x * 256 + threadIdx.x;
    const float4* p = (const float4*)&g_part[0][0][0][0];
    const int stride = Bn * Qn * DVn / 4;  // 65536
    float4 s = p[idx];
#pragma unroll
    for (int c = 1; c < 8; c++) {
        float4 t = p[idx + c * stride];
        s.x += t.x; s.y += t.y; s.z += t.z; s.w += t.w;
    }
    ((float4*)out)[idx] = s;
}

// ---------------------------------------------------------------------------
extern "C" void kernel_launch(void* const* d_in, const int* in_sizes, int n_in,
                              void* d_out, int out_size) {
    const float* queries = (const float*)d_in[0];
    const float* keys    = (const float*)d_in[1];
    const float* values  = (const float*)d_in[2];
    const int*   vlens   = (const int*)d_in[3];
    const float* Wq      = (const float*)d_in[4];
    const float* Wk      = (const float*)d_in[5];
    const float* wv      = (const float*)d_in[6];
    float* out           = (float*)d_out;

    proj_mma_kernel<<<136, 256>>>(keys, queries, Wk, Wq);
    scores_kernel<<<dim3(Kn / 32, 2, Bn), 256>>>(wv);
    softmax_kernel<<<dim3(Qn, Bn), 256>>>(vlens);
    av_mma_kernel<<<dim3(8, 2, Bn), 256>>>(values, vlens);
    reduce_kernel<<<256, 256>>>(out);
}

// round 10
// speedup vs baseline: 1.5152x; 1.5152x over previous
#include <cuda_runtime.h>
#include <cuda_bf16.h>
#include <cstdint>

#define Bn  16
#define Qn  64
#define Kn  1024
#define Dn  256
#define Hn  128
#define DVn 256

// Scratch (device globals; no allocation allowed in kernel_launch)
__device__ float g_kproj[Bn * Kn * Hn];        // 8 MB
__device__ float g_qproj[Bn * Qn * Hn];        // 0.5 MB
__device__ float g_scores[Bn * Qn * Kn];       // 4 MB (scores, then attn)
__device__ float g_part[8][Bn][Qn][DVn];       // 8 MB AV partials (zero-init;
                                               // chunks beyond vlen are never
                                               // written and stay exactly 0)

__device__ __forceinline__ float fast_tanh(float x) {
    float y;
    asm("tanh.approx.f32 %0, %1;" : "=f"(y) : "f"(x));
    return y;
}

// ---------------------------------------------------------------------------
// mma.sync m16n8k16 bf16 (row.col) fp32 accum; ldmatrix fragment loaders.
// All compute_80+ PTX (the harness's compute_100 virtual target rejects
// tcgen05; these pass).
// ---------------------------------------------------------------------------
__device__ __forceinline__ void mma16816(float* d, const uint32_t* a,
                                         const uint32_t* b) {
    asm volatile(
        "mma.sync.aligned.m16n8k16.row.col.f32.bf16.bf16.f32 "
        "{%0,%1,%2,%3}, {%4,%5,%6,%7}, {%8,%9}, {%0,%1,%2,%3};"
        : "+f"(d[0]), "+f"(d[1]), "+f"(d[2]), "+f"(d[3])
        : "r"(a[0]), "r"(a[1]), "r"(a[2]), "r"(a[3]), "r"(b[0]), "r"(b[1]));
}

// A fragment (16x16, row-major source): r0..r3 = a0..a3.
__device__ __forceinline__ void ldm_x4(uint32_t* r, const __nv_bfloat16* p) {
    uint32_t a = (uint32_t)__cvta_generic_to_shared(p);
    asm volatile(
        "ldmatrix.sync.aligned.m8n8.x4.shared.b16 {%0,%1,%2,%3}, [%4];"
        : "=r"(r[0]), "=r"(r[1]), "=r"(r[2]), "=r"(r[3]) : "r"(a));
}
// B fragments for TWO adjacent n-tiles from [k][n]-layout source (transposed
// in-flight): {r0,r1} = n-tile j, {r2,r3} = n-tile j+1.
__device__ __forceinline__ void ldm_x4t(uint32_t* r, const __nv_bfloat16* p) {
    uint32_t a = (uint32_t)__cvta_generic_to_shared(p);
    asm volatile(
        "ldmatrix.sync.aligned.m8n8.x4.trans.shared.b16 {%0,%1,%2,%3}, [%4];"
        : "=r"(r[0]), "=r"(r[1]), "=r"(r[2]), "=r"(r[3]) : "r"(a));
}

__device__ __forceinline__ __nv_bfloat162 hi2(float a, float b) {
    return __halves2bfloat162(__float2bfloat16(a), __float2bfloat16(b));
}
__device__ __forceinline__ __nv_bfloat162 lo2(float a, float b) {
    return __halves2bfloat162(
        __float2bfloat16(a - __bfloat162float(__float2bfloat16(a))),
        __float2bfloat16(b - __bfloat162float(__float2bfloat16(b))));
}

#define KC 32
#define APAD 40   // A tiles [m][32+8]: row stride 20 words -> ldmatrix phases
                  // hit distinct 4-word windows (20r mod 32 all distinct)
#define WPAD 136  // W tile [32][128+8]: row stride 68 words mod 32 = 4 ->
                  // 8-row ldmatrix phase covers banks 0..31 exactly once
#define VPAD 264  // V tile [32][256+8]: row stride 132 words mod 32 = 4

// ---------------------------------------------------------------------------
// Projection P[r, h] = sum_d X[r, d] * W[d, h] via HMMA, split-bf16 3-product.
// R10: W staged in natural [d][h] layout (conflict-free stores; R9's
// transposed scatter was 16-way bank-conflicted) + ldmatrix fragments +
// register prefetch of the next k-chunk under the MMA section.
// Grid 136 CTAs; tile 128m x 128n; 8 warps 2(M)x4(N), warp tile 64x32.
// ---------------------------------------------------------------------------
__global__ void __launch_bounds__(256, 1) proj_mma_kernel(
    const float* __restrict__ keys, const float* __restrict__ queries,
    const float* __restrict__ Wk, const float* __restrict__ Wq) {
    __shared__ __align__(16) __nv_bfloat16 sAh[128][APAD];
    __shared__ __align__(16) __nv_bfloat16 sAl[128][APAD];
    __shared__ __align__(16) __nv_bfloat16 sWh[32][WPAD];  // [d][h] natural
    __shared__ __align__(16) __nv_bfloat16 sWl[32][WPAD];

    const int tid  = threadIdx.x;
    const int wid  = tid >> 5;
    const int lane = tid & 31;
    const int cid  = blockIdx.x;

    const float* X;
    const float* W;
    float* P;
    int row0;
    if (cid < 128) {
        X = keys; W = Wk; P = g_kproj; row0 = cid * 128;
    } else {
        X = queries; W = Wq; P = g_qproj; row0 = (cid - 128) * 128;
    }

    const int wm   = (wid & 1) * 64;
    const int wn   = (wid >> 1) * 32;
    const int gid  = lane >> 2;
    const int tig  = lane & 3;
    const int lrow = lane & 15;       // ldmatrix row-within-16
    const int lcol = (lane >> 4) * 8; // ldmatrix col-half

    float acc[4][4][4];
#pragma unroll
    for (int im = 0; im < 4; im++)
#pragma unroll
        for (int j = 0; j < 4; j++)
#pragma unroll
            for (int r = 0; r < 4; r++) acc[im][j][r] = 0.f;

    float4 xPre[4], wPre[4];
    // prefetch chunk 0
#pragma unroll
    for (int i = 0; i < 4; i++) {
        int idx = tid + i * 256;
        int r = idx >> 3, kq = idx & 7;
        xPre[i] = *(const float4*)&X[(size_t)(row0 + r) * Dn + kq * 4];
    }
#pragma unroll
    for (int i = 0; i < 4; i++) {
        int idx = tid + i * 256;
        int k = idx >> 5, n4 = idx & 31;
        wPre[i] = *(const float4*)&W[(size_t)k * Hn + n4 * 4];
    }

    for (int kc = 0; kc < Dn; kc += KC) {
        // ---- convert prefetched regs -> smem ----
#pragma unroll
        for (int i = 0; i < 4; i++) {
            int idx = tid + i * 256;
            int r = idx >> 3, kq = idx & 7;
            float4 v = xPre[i];
            *(__nv_bfloat162*)&sAh[r][kq * 4]     = hi2(v.x, v.y);
            *(__nv_bfloat162*)&sAh[r][kq * 4 + 2] = hi2(v.z, v.w);
            *(__nv_bfloat162*)&sAl[r][kq * 4]     = lo2(v.x, v.y);
            *(__nv_bfloat162*)&sAl[r][kq * 4 + 2] = lo2(v.z, v.w);
        }
#pragma unroll
        for (int i = 0; i < 4; i++) {
            int idx = tid + i * 256;
            int k = idx >> 5, n4 = idx & 31;
            float4 v = wPre[i];
            *(__nv_bfloat162*)&sWh[k][n4 * 4]     = hi2(v.x, v.y);
            *(__nv_bfloat162*)&sWh[k][n4 * 4 + 2] = hi2(v.z, v.w);
            *(__nv_bfloat162*)&sWl[k][n4 * 4]     = lo2(v.x, v.y);
            *(__nv_bfloat162*)&sWl[k][n4 * 4 + 2] = lo2(v.z, v.w);
        }
        __syncthreads();

        // ---- prefetch next chunk (overlaps the MMA section) ----
        if (kc + KC < Dn) {
#pragma unroll
            for (int i = 0; i < 4; i++) {
                int idx = tid + i * 256;
                int r = idx >> 3, kq = idx & 7;
                xPre[i] = *(const float4*)
                    &X[(size_t)(row0 + r) * Dn + kc + KC + kq * 4];
            }
#pragma unroll
            for (int i = 0; i < 4; i++) {
                int idx = tid + i * 256;
                int k = idx >> 5, n4 = idx & 31;
                wPre[i] = *(const float4*)
                    &W[(size_t)(kc + KC + k) * Hn + n4 * 4];
            }
        }

        // ---- MMA: 2 k16 steps ----
#pragma unroll
        for (int s = 0; s < 2; s++) {
            uint32_t Ah[4][4], Al[4][4];
#pragma unroll
            for (int im = 0; im < 4; im++) {
                ldm_x4(Ah[im], &sAh[wm + im * 16 + lrow][s * 16 + lcol]);
                ldm_x4(Al[im], &sAl[wm + im * 16 + lrow][s * 16 + lcol]);
            }
            uint32_t Bh[4][2], Bl[4][2];
#pragma unroll
            for (int jj = 0; jj < 2; jj++) {
                uint32_t t[4];
                ldm_x4t(t, &sWh[s * 16 + lrow][wn + jj * 16 + lcol]);
                Bh[jj * 2][0] = t[0]; Bh[jj * 2][1] = t[1];
                Bh[jj * 2 + 1][0] = t[2]; Bh[jj * 2 + 1][1] = t[3];
                ldm_x4t(t, &sWl[s * 16 + lrow][wn + jj * 16 + lcol]);
                Bl[jj * 2][0] = t[0]; Bl[jj * 2][1] = t[1];
                Bl[jj * 2 + 1][0] = t[2]; Bl[jj * 2 + 1][1] = t[3];
            }
#pragma unroll
            for (int im = 0; im < 4; im++) {
#pragma unroll
                for (int j = 0; j < 4; j++) {
                    mma16816(acc[im][j], Ah[im], Bh[j]);
                    mma16816(acc[im][j], Al[im], Bh[j]);
                    mma16816(acc[im][j], Ah[im], Bl[j]);
                }
            }
        }
        __syncthreads();
    }

#pragma unroll
    for (int im = 0; im < 4; im++) {
        int r_lo = row0 + wm + im * 16 + gid;
#pragma unroll
        for (int j = 0; j < 4; j++) {
            int c = wn + j * 8 + tig * 2;
            *(float2*)&P[(size_t)r_lo * Hn + c] =
                make_float2(acc[im][j][0], acc[im][j][1]);
            *(float2*)&P[(size_t)(r_lo + 8) * Hn + c] =
                make_float2(acc[im][j][2], acc[im][j][3]);
        }
    }
}

// ---------------------------------------------------------------------------
// scores[b, q, k] = sum_h wv[h] * tanh(qproj[b,q,h] + kproj[b,k,h])
// fp32 tanh.approx (R9's f16x2 gave no measurable win and 40x worse error).
// CTA = (k-tile 32, q-half 32, b).
// ---------------------------------------------------------------------------
__global__ void scores_kernel(const float* __restrict__ wv) {
    const int b   = blockIdx.z;
    const int qh  = blockIdx.y * 32;
    const int k0  = blockIdx.x * 32;
    const int tid = threadIdx.x;

    __shared__ __align__(16) float sQ[32][Hn];
    __shared__ __align__(16) float sK[32][132];
    __shared__ __align__(16) float sWv[Hn];

    {
        const float4* src =
            (const float4*)(g_qproj + ((size_t)b * Qn + qh) * Hn);
        float4* dst = (float4*)&sQ[0][0];
#pragma unroll
        for (int i = 0; i < 4; i++) {
            int j = tid + i * 256;
            dst[j] = src[j];
        }
    }
    {
        const float4* src =
            (const float4*)(g_kproj + ((size_t)b * Kn + k0) * Hn);
#pragma unroll
        for (int i = 0; i < 4; i++) {
            int j   = tid + i * 256;
            int row = j >> 5;
            int c4  = j & 31;
            *(float4*)&sK[row][c4 * 4] = src[j];
        }
    }
    if (tid < Hn) sWv[tid] = wv[tid];
    __syncthreads();

    const int kk = tid & 31;
    const int q0 = (tid >> 5) * 4;
    float sc[4];
    sc[0] = sc[1] = sc[2] = sc[3] = 0.f;

#pragma unroll 4
    for (int h = 0; h < Hn; h += 4) {
        float4 kv = *(const float4*)&sK[kk][h];
        float4 w4 = *(const float4*)&sWv[h];
#pragma unroll
        for (int qi = 0; qi < 4; qi++) {
            float4 qv = *(const float4*)&sQ[q0 + qi][h];
            sc[qi] += w4.x * fast_tanh(qv.x + kv.x);
            sc[qi] += w4.y * fast_tanh(qv.y + kv.y);
            sc[qi] += w4.z * fast_tanh(qv.z + kv.z);
            sc[qi] += w4.w * fast_tanh(qv.w + kv.w);
        }
    }

    float* srow = g_scores + ((size_t)b * Qn + qh) * Kn + k0 + kk;
#pragma unroll
    for (int qi = 0; qi < 4; qi++) {
        srow[(size_t)(q0 + qi) * Kn] = sc[qi];
    }
}

// ---------------------------------------------------------------------------
// Masked softmax over K=1024, in place in g_scores.
// Invalid lanes (k >= vlen) -> exactly 0 after exp underflow.
// ---------------------------------------------------------------------------
__global__ void softmax_kernel(const int* __restrict__ vlen) {
    const int b   = blockIdx.y;
    const int q   = blockIdx.x;
    const int tid = threadIdx.x;

    float* row   = g_scores + ((size_t)b * Qn + q) * Kn;
    const int vl = vlen[b];

    float4 s      = ((const float4*)row)[tid];
    const int kb  = tid * 4;
    if (kb + 0 >= vl) s.x = -1e6f;
    if (kb + 1 >= vl) s.y = -1e6f;
    if (kb + 2 >= vl) s.z = -1e6f;
    if (kb + 3 >= vl) s.w = -1e6f;

    __shared__ float redm[8];
    __shared__ float reds[8];

    float m = fmaxf(fmaxf(s.x, s.y), fmaxf(s.z, s.w));
#pragma unroll
    for (int o = 16; o; o >>= 1) m = fmaxf(m, __shfl_xor_sync(0xffffffffu, m, o));
    if ((tid & 31) == 0) redm[tid >> 5] = m;
    __syncthreads();
    float M = redm[0];
#pragma unroll
    for (int i = 1; i < 8; i++) M = fmaxf(M, redm[i]);

    float e0 = __expf(s.x - M);
    float e1 = __expf(s.y - M);
    float e2 = __expf(s.z - M);
    float e3 = __expf(s.w - M);

    float t = (e0 + e1) + (e2 + e3);
#pragma unroll
    for (int o = 16; o; o >>= 1) t += __shfl_xor_sync(0xffffffffu, t, o);
    if ((tid & 31) == 0) reds[tid >> 5] = t;
    __syncthreads();
    float S = reds[0];
#pragma unroll
    for (int i = 1; i < 8; i++) S += reds[i];

    float inv = 1.0f / S;
    ((float4*)row)[tid] = make_float4(e0 * inv, e1 * inv, e2 * inv, e3 * inv);
}

// ---------------------------------------------------------------------------
// AV as HMMA GEMM. R10: back to R7 grid (8 k-chunks, Bn) = 128 CTAs, tile
// 64q x 256dv over 128 k; V staged in natural [k][n] layout (conflict-free;
// the old transposed scatter was 16-way conflicted) + ldmatrix fragments +
// register prefetch. Chunks beyond vlen exit early (partials stay 0).
// 8 warps 2(M) x 4(N); warp tile 32q x 64n.
// ---------------------------------------------------------------------------
__global__ void __launch_bounds__(256, 1) av_mma_kernel(
    const float* __restrict__ V, const int* __restrict__ vlen) {
    const int b  = blockIdx.y;
    const int ck = blockIdx.x;
    const int k0 = ck * 128;
    if (k0 >= vlen[b]) return;  // uniform per CTA

    __shared__ __align__(16) __nv_bfloat16 sAh[64][APAD];  // attn [q][k]
    __shared__ __align__(16) __nv_bfloat16 sAl[64][APAD];
    __shared__ __align__(16) __nv_bfloat16 sVh[32][VPAD];  // V [k][n] natural
    __shared__ __align__(16) __nv_bfloat16 sVl[32][VPAD];

    const int tid  = threadIdx.x;
    const int wid  = tid >> 5;
    const int lane = tid & 31;
    const int gid  = lane >> 2;
    const int tig  = lane & 3;
    const int lrow = lane & 15;
    const int lcol = (lane >> 4) * 8;
    const int wm   = (wid & 1) * 32;   // 2 x 32 = 64 q
    const int wn   = (wid >> 1) * 64;  // 4 x 64 = 256 dv

    float acc[2][8][4];
#pragma unroll
    for (int im = 0; im < 2; im++)
#pragma unroll
        for (int j = 0; j < 8; j++)
#pragma unroll
            for (int r = 0; r < 4; r++) acc[im][j][r] = 0.f;

    const float* Ab = g_scores + ((size_t)b * Qn) * Kn + k0;
    const float* Vb = V + ((size_t)b * Kn + k0) * DVn;

    float4 aPre[2], vPre[8];
    // prefetch chunk 0
#pragma unroll
    for (int i = 0; i < 2; i++) {
        int idx = tid + i * 256;
        int r = idx >> 3, kq = idx & 7;
        aPre[i] = *(const float4*)&Ab[(size_t)r * Kn + kq * 4];
    }
#pragma unroll
    for (int i = 0; i < 8; i++) {
        int idx = tid + i * 256;
        int k = idx >> 6, n4 = idx & 63;
        vPre[i] = *(const float4*)&Vb[(size_t)k * DVn + n4 * 4];
    }

    for (int kc = 0; kc < 128; kc += KC) {
        // ---- convert prefetched regs -> smem ----
#pragma unroll
        for (int i = 0; i < 2; i++) {
            int idx = tid + i * 256;
            int r = idx >> 3, kq = idx & 7;
            float4 v = aPre[i];
            *(__nv_bfloat162*)&sAh[r][kq * 4]     = hi2(v.x, v.y);
            *(__nv_bfloat162*)&sAh[r][kq * 4 + 2] = hi2(v.z, v.w);
            *(__nv_bfloat162*)&sAl[r][kq * 4]     = lo2(v.x, v.y);
            *(__nv_bfloat162*)&sAl[r][kq * 4 + 2] = lo2(v.z, v.w);
        }
#pragma unroll
        for (int i = 0; i < 8; i++) {
            int idx = tid + i * 256;
            int k = idx >> 6, n4 = idx & 63;
            float4 v = vPre[i];
            *(__nv_bfloat162*)&sVh[k][n4 * 4]     = hi2(v.x, v.y);
            *(__nv_bfloat162*)&sVh[k][n4 * 4 + 2] = hi2(v.z, v.w);
            *(__nv_bfloat162*)&sVl[k][n4 * 4]     = lo2(v.x, v.y);
            *(__nv_bfloat162*)&sVl[k][n4 * 4 + 2] = lo2(v.z, v.w);
        }
        __syncthreads();

        // ---- prefetch next chunk ----
        if (kc + KC < 128) {
#pragma unroll
            for (int i = 0; i < 2; i++) {
                int idx = tid + i * 256;
                int r = idx >> 3, kq = idx & 7;
                aPre[i] = *(const float4*)
                    &Ab[(size_t)r * Kn + kc + KC + kq * 4];
            }
#pragma unroll
            for (int i = 0; i < 8; i++) {
                int idx = tid + i * 256;
                int k = idx >> 6, n4 = idx & 63;
                vPre[i] = *(const float4*)
                    &Vb[(size_t)(kc + KC + k) * DVn + n4 * 4];
            }
        }

        // ---- MMA: 2 k16 steps ----
#pragma unroll
        for (int s = 0; s < 2; s++) {
            uint32_t Ah2[2][4], Al2[2][4];
#pragma unroll
            for (int im = 0; im < 2; im++) {
                ldm_x4(Ah2[im], &sAh[wm + im * 16 + lrow][s * 16 + lcol]);
                ldm_x4(Al2[im], &sAl[wm + im * 16 + lrow][s * 16 + lcol]);
            }
            uint32_t Bh[8][2], Bl[8][2];
#pragma unroll
            for (int jj = 0; jj < 4; jj++) {
                uint32_t t[4];
                ldm_x4t(t, &sVh[s * 16 + lrow][wn + jj * 16 + lcol]);
                Bh[jj * 2][0] = t[0]; Bh[jj * 2][1] = t[1];
                Bh[jj * 2 + 1][0] = t[2]; Bh[jj * 2 + 1][1] = t[3];
                ldm_x4t(t, &sVl[s * 16 + lrow][wn + jj * 16 + lcol]);
                Bl[jj * 2][0] = t[0]; Bl[jj * 2][1] = t[1];
                Bl[jj * 2 + 1][0] = t[2]; Bl[jj * 2 + 1][1] = t[3];
            }
#pragma unroll
            for (int im = 0; im < 2; im++) {
#pragma unroll
                for (int j = 0; j < 8; j++) {
                    mma16816(acc[im][j], Ah2[im], Bh[j]);
                    mma16816(acc[im][j], Al2[im], Bh[j]);
                    mma16816(acc[im][j], Ah2[im], Bl[j]);
                }
            }
        }
        __syncthreads();
    }

    // ---- epilogue: partials to g_part[ck][b] ----
    float* Pb = &g_part[ck][b][0][0];
#pragma unroll
    for (int im = 0; im < 2; im++) {
        int r = wm + im * 16 + gid;
#pragma unroll
        for (int j = 0; j < 8; j++) {
            int c = wn + j * 8 + tig * 2;
            *(float2*)&Pb[(size_t)r * DVn + c] =
                make_float2(acc[im][j][0], acc[im][j][1]);
            *(float2*)&Pb[(size_t)(r + 8) * DVn + c] =
                make_float2(acc[im][j][2], acc[im][j][3]);
        }
    }
}

// ---------------------------------------------------------------------------
// out = sum over 8 k-chunk partials. 256 CTAs x 256 threads x 1 float4.
// ---------------------------------------------------------------------------
__global__ void reduce_kernel(float* __restrict__ out) {
    const int idx = blockIdx.x * 256 + threadIdx.x;
    const float4* p = (const float4*)&g_part[0][0][0][0];
    const int stride = Bn * Qn * DVn / 4;  // 65536
    float4 s = p[idx];
#pragma unroll
    for (int c = 1; c < 8; c++) {
        float4 t = p[idx + c * stride];
        s.x += t.x; s.y += t.y; s.z += t.z; s.w += t.w;
    }
    ((float4*)out)[idx] = s;
}

// ---------------------------------------------------------------------------
extern "C" void kernel_launch(void* const* d_in, const int* in_sizes, int n_in,
                              void* d_out, int out_size) {
    const float* queries = (const float*)d_in[0];
    const float* keys    = (const float*)d_in[1];
    const float* values  = (const float*)d_in[2];
    const int*   vlens   = (const int*)d_in[3];
    const float* Wq      = (const float*)d_in[4];
    const float* Wk      = (const float*)d_in[5];
    const float* wv      = (const float*)d_in[6];
    float* out           = (float*)d_out;

    proj_mma_kernel<<<136, 256>>>(keys, queries, Wk, Wq);
    scores_kernel<<<dim3(Kn / 32, 2, Bn), 256>>>(wv);
    softmax_kernel<<<dim3(Qn, Bn), 256>>>(vlens);
    av_mma_kernel<<<dim3(8, Bn), 256>>>(values, vlens);
    reduce_kernel<<<256, 256>>>(out);
}